// round 4
// baseline (speedup 1.0000x reference)
#include <cuda_runtime.h>

// GRU persistent kernel, fp32 CUDA-core baseline.
// B=128, T=1024, I=256, H=512. Grid = 128 CTAs (4 batch tiles x 32 j tiles),
// 256 threads each, single wave => software grid barrier is safe.

#define BB 128
#define TT 1024
#define II 256
#define HH 512

#define BM 32          // batch rows per CTA
#define BJ 16          // j columns per CTA
#define NROWS 48       // 3 gates * BJ weight rows per CTA
#define KTOT 768       // II + HH
#define KC 128         // k-chunk staged in SMEM
#define WST 772        // padded W row stride (floats)
#define VST 132        // padded V row stride (floats)
#define NTHREADS 256
#define GRID 128

// Scratch state (device globals: no allocations allowed in kernel_launch)
__device__ float g_hbuf[2][BB * HH];
__device__ int g_count;            // barrier arrival counter (reset each launch)
__device__ volatile int g_flag;    // barrier release phase   (reset each launch)

__global__ void __launch_bounds__(NTHREADS, 1) gru_persistent(
    const float* __restrict__ x,    // (B, T, I)
    const float* __restrict__ h0,   // (1, B, H)
    const float* __restrict__ Wih,  // (3H, I)
    const float* __restrict__ bih,  // (3H)
    const float* __restrict__ Whh,  // (3H, H)
    const float* __restrict__ bhh,  // (3H)
    float* __restrict__ out)        // (B,1,4H) then (1,B,4H) concatenated
{
    extern __shared__ float smem[];
    float* Wt = smem;                    // [NROWS][WST]  resident weights
    float* Vt = smem + NROWS * WST;      // [BM][VST]     staged input chunk

    const int cta = blockIdx.x;
    const int cm  = cta & 3;             // batch tile 0..3
    const int cn  = cta >> 2;            // j tile 0..31
    const int bm0 = cm * BM;
    const int j0  = cn * BJ;
    const int tid = threadIdx.x;
    const int tx  = tid & 15;            // j_local
    const int ty  = tid >> 4;            // m pair index
    const int m0  = 2 * ty;
    const int m1  = 2 * ty + 1;
    const int j   = j0 + tx;

    // ---- Load weight slice into SMEM once (rows: gate*16 + j_local) ----
    for (int idx = tid; idx < NROWS * KTOT; idx += NTHREADS) {
        int row = idx / KTOT;
        int k   = idx - row * KTOT;
        int g   = (row >> 4) * HH + j0 + (row & 15);   // global gate row
        float v = (k < II) ? Wih[g * II + k] : Whh[g * HH + (k - II)];
        Wt[row * WST + k] = v;
    }

    // Per-thread constant biases for column j
    const float rb  = bih[j]          + bhh[j];
    const float zb  = bih[HH + j]     + bhh[HH + j];
    const float nbi = bih[2 * HH + j];
    const float nbh = bhh[2 * HH + j];
    __syncthreads();

#define STAGE(SRCEXPR)                                                   \
    __syncthreads();                                                     \
    {                                                                    \
        _Pragma("unroll")                                                \
        for (int q = tid; q < BM * (KC / 4); q += NTHREADS) {            \
            int m  = q >> 5;                                             \
            int kf = q & 31;                                             \
            float4 val = (SRCEXPR);                                      \
            *(float4*)(Vt + m * VST + kf * 4) = val;                     \
        }                                                                \
    }                                                                    \
    __syncthreads();

#define COMPUTE(ACC, KBASE)                                              \
    {                                                                    \
        _Pragma("unroll 8")                                              \
        for (int ks = 0; ks < KC; ks += 4) {                             \
            float4 va = *(const float4*)(Vt + m0 * VST + ks);            \
            float4 vb = *(const float4*)(Vt + m1 * VST + ks);            \
            const float* wb = Wt + (KBASE) + ks;                         \
            float4 w0 = *(const float4*)(wb + (tx)      * WST);          \
            float4 w1 = *(const float4*)(wb + (tx + 16) * WST);          \
            float4 w2 = *(const float4*)(wb + (tx + 32) * WST);          \
            ACC[0][0] += va.x*w0.x + va.y*w0.y + va.z*w0.z + va.w*w0.w;  \
            ACC[0][1] += va.x*w1.x + va.y*w1.y + va.z*w1.z + va.w*w1.w;  \
            ACC[0][2] += va.x*w2.x + va.y*w2.y + va.z*w2.z + va.w*w2.w;  \
            ACC[1][0] += vb.x*w0.x + vb.y*w0.y + vb.z*w0.z + vb.w*w0.w;  \
            ACC[1][1] += vb.x*w1.x + vb.y*w1.y + vb.z*w1.z + vb.w*w1.w;  \
            ACC[1][2] += vb.x*w2.x + vb.y*w2.y + vb.z*w2.z + vb.w*w2.w;  \
        }                                                                \
    }

    for (int t = 0; t < TT; t++) {
        const float* hread  = (t == 0) ? h0 : g_hbuf[(t - 1) & 1];
        float*       hwrite = g_hbuf[t & 1];

        float aX[2][3] = {{0.f,0.f,0.f},{0.f,0.f,0.f}};
        float aH[2][3] = {{0.f,0.f,0.f},{0.f,0.f,0.f}};

        const float hp0 = hread[(bm0 + m0) * HH + j];
        const float hp1 = hread[(bm0 + m1) * HH + j];

        // x phase: k in [0, 256)
        #pragma unroll
        for (int kc = 0; kc < 2; kc++) {
            STAGE(*(const float4*)(x + ((size_t)(bm0 + m) * TT + t) * II
                                     + kc * KC + kf * 4))
            COMPUTE(aX, kc * KC)
        }
        // h phase: k in [0, 512)
        #pragma unroll
        for (int kc = 0; kc < 4; kc++) {
            STAGE(*(const float4*)(hread + (size_t)(bm0 + m) * HH
                                         + kc * KC + kf * 4))
            COMPUTE(aH, II + kc * KC)
        }

        // ---- Gates (fully in-register; thread owns r,z,n for (b, j)) ----
        #pragma unroll
        for (int mi = 0; mi < 2; mi++) {
            const int   b  = bm0 + m0 + mi;
            const float hp = mi ? hp1 : hp0;
            float r  = 1.f / (1.f + __expf(-(aX[mi][0] + aH[mi][0] + rb)));
            float z  = 1.f / (1.f + __expf(-(aX[mi][1] + aH[mi][1] + zb)));
            float nn = tanhf(aX[mi][2] + nbi + r * (aH[mi][2] + nbh));
            float hn = (1.f - z) * nn + z * hp;
            hwrite[b * HH + j] = hn;
            if (t == TT - 1) {
                int o  = b * (4 * HH) + j;
                int o2 = o + BB * 4 * HH;
                out[o]            = r;  out[o2]            = r;
                out[o + HH]       = z;  out[o2 + HH]       = z;
                out[o + 2 * HH]   = nn; out[o2 + 2 * HH]   = nn;
                out[o + 3 * HH]   = hn; out[o2 + 3 * HH]   = hn;
            }
        }

        // ---- Grid barrier (flag/counter; single-wave residency) ----
        if (t < TT - 1) {
            __threadfence();
            __syncthreads();
            if (tid == 0) {
                int old = atomicAdd(&g_count, 1);
                if (old == GRID - 1) {
                    g_count = 0;
                    __threadfence();
                    g_flag = t + 1;
                } else {
                    while (g_flag < t + 1) { }
                    __threadfence();
                }
            }
            __syncthreads();
        }
    }

    // ---- Cleanup barrier state for the next launch (no spin) ----
    __syncthreads();
    if (tid == 0) {
        int old = atomicAdd(&g_count, 1);
        if (old == GRID - 1) {
            g_count = 0;
            g_flag  = 0;
            __threadfence();
        }
    }
}

extern "C" void kernel_launch(void* const* d_in, const int* in_sizes, int n_in,
                              void* d_out, int out_size) {
    const float* x   = (const float*)d_in[0];
    const float* h   = (const float*)d_in[1];
    const float* Wih = (const float*)d_in[2];
    const float* bih = (const float*)d_in[3];
    const float* Whh = (const float*)d_in[4];
    const float* bhh = (const float*)d_in[5];
    float* out = (float*)d_out;

    const int smem_bytes = (NROWS * WST + BM * VST) * 4;
    cudaFuncSetAttribute(gru_persistent,
                         cudaFuncAttributeMaxDynamicSharedMemorySize,
                         smem_bytes);
    gru_persistent<<<GRID, NTHREADS, smem_bytes>>>(x, h, Wih, bih, Whh, bhh, out);
}

// round 7
// speedup vs baseline: 2.1972x; 2.1972x over previous
#include <cuda_runtime.h>
#include <cuda_bf16.h>
#include <stdint.h>

// GRU persistent scan on warp-level bf16 MMA (mma.sync m16n8k16, sm_80 ISA —
// safe on the plain-sm_103 ptxas target that rejected tcgen05).
// B=128, T=1024, I=256, H=512. 128 CTAs x 128 threads, single wave.
// fp32 accuracy via bf16 hi/lo split: hi*Whi + hi*Wlo + lo*Whi.

#define TT 1024
#define II 256
#define HHID 512
#define NB 128
#define GRID 128
#define NTHREADS 128
#define WSTRIDE 776                       // halfs per W row (pad: conflict-free ldmatrix)
#define WLO   (48 * WSTRIDE * 2)          // byte offset of lo component
#define WBYTES (48 * WSTRIDE * 2 * 2)     // hi + lo
#define NSCR  (48 * 33)
#define SMEM_BYTES (WBYTES + (2 * NSCR + 64) * 4)

__device__ float g_h[2][NB * HHID];
__device__ int g_count;
__device__ volatile int g_flag;

__device__ __forceinline__ uint32_t smem_u32(const void* p) {
    uint32_t a;
    asm("{ .reg .u64 t; cvta.to.shared.u64 t, %1; cvt.u32.u64 %0, t; }"
        : "=r"(a) : "l"(p));
    return a;
}
__device__ __forceinline__ void ldsm4(uint32_t a, unsigned& r0, unsigned& r1,
                                      unsigned& r2, unsigned& r3) {
    asm volatile("ldmatrix.sync.aligned.m8n8.x4.shared.b16 {%0,%1,%2,%3}, [%4];"
                 : "=r"(r0), "=r"(r1), "=r"(r2), "=r"(r3) : "r"(a));
}
__device__ __forceinline__ void ldsm2(uint32_t a, unsigned& r0, unsigned& r1) {
    asm volatile("ldmatrix.sync.aligned.m8n8.x2.shared.b16 {%0,%1}, [%2];"
                 : "=r"(r0), "=r"(r1) : "r"(a));
}
__device__ __forceinline__ void mma_bf16(float* d, const unsigned* a,
                                         unsigned b0, unsigned b1) {
    asm volatile("mma.sync.aligned.m16n8k16.row.col.f32.bf16.bf16.f32 "
                 "{%0,%1,%2,%3}, {%4,%5,%6,%7}, {%8,%9}, {%0,%1,%2,%3};"
                 : "+f"(d[0]), "+f"(d[1]), "+f"(d[2]), "+f"(d[3])
                 : "r"(a[0]), "r"(a[1]), "r"(a[2]), "r"(a[3]), "r"(b0), "r"(b1));
}
__device__ __forceinline__ void cvt_hilo(float2 v, unsigned& hi, unsigned& lo) {
    __nv_bfloat162 h2 = __float22bfloat162_rn(v);
    float2 hf = __bfloat1622float2(h2);
    __nv_bfloat162 l2 = __float22bfloat162_rn(make_float2(v.x - hf.x, v.y - hf.y));
    hi = reinterpret_cast<unsigned&>(h2);
    lo = reinterpret_cast<unsigned&>(l2);
}

__global__ void __launch_bounds__(NTHREADS, 1) gru_mma(
    const float* __restrict__ x,    // (B, T, I)
    const float* __restrict__ h0,   // (1, B, H)
    const float* __restrict__ Wih,  // (3H, I)
    const float* __restrict__ bih,
    const float* __restrict__ Whh,  // (3H, H)
    const float* __restrict__ bhh,
    float* __restrict__ out)        // (B,1,4H) ++ (1,B,4H)
{
    extern __shared__ char smc[];
    const int tid  = threadIdx.x;
    const int lane = tid & 31;
    const int w    = tid >> 5;
    const int bm0  = (blockIdx.x & 3) * 32;
    const int j0   = (blockIdx.x >> 2) * 16;
    const int wm   = (w & 1) * 16;      // warp m offset (0/16)
    const int wn   = (w >> 1) * 24;     // warp n offset (0/24)

    // ---- resident weights, bf16 hi/lo, rows n = gate*16 + jl ----
    __nv_bfloat16* Whi_s = (__nv_bfloat16*)smc;
    __nv_bfloat16* Wlo_s = (__nv_bfloat16*)(smc + WLO);
    for (int idx = tid; idx < 48 * 768; idx += NTHREADS) {
        int n = idx / 768, k = idx - n * 768;
        int g = (n >> 4) * HHID + j0 + (n & 15);
        float v = (k < II) ? Wih[g * II + k] : Whh[g * HHID + (k - II)];
        __nv_bfloat16 hi = __float2bfloat16(v);
        Whi_s[n * WSTRIDE + k] = hi;
        Wlo_s[n * WSTRIDE + k] = __float2bfloat16(v - __bfloat162float(hi));
    }
    float* scrX = (float*)(smc + WBYTES);
    float* scrH = scrX + NSCR;
    float* bias = scrX + 2 * NSCR;
    if (tid < 16) {
        int j = j0 + tid;
        bias[tid]      = bih[j]            + bhh[j];
        bias[16 + tid] = bih[HHID + j]     + bhh[HHID + j];
        bias[32 + tid] = bih[2 * HHID + j];
        bias[48 + tid] = bhh[2 * HHID + j];
    }
    __syncthreads();

    // ---- ldmatrix base addresses (per-thread, k added per step) ----
    const uint32_t sW = smem_u32(smc);
    {
    }
    const int q  = lane & 7;
    const int mi = lane >> 3;
    const uint32_t a4base = sW + (uint32_t)(((wn + 8 * (mi >> 1) + q) * WSTRIDE
                                             + 8 * (mi & 1)) * 2);
    const uint32_t a2base = sW + (uint32_t)(((wn + 16 + q) * WSTRIDE
                                             + 8 * (mi & 1)) * 2);

    // ---- A-fragment global bases ----
    const int rl = lane >> 2;
    const int c2 = (lane & 3) * 2;
    const float* bx0 = x + (size_t)(bm0 + wm + rl) * TT * II + c2;
    const float* bx1 = bx0 + (size_t)8 * TT * II;

    // ---- gate-thread state ----
    const int mg  = (tid >> 4) * 4;
    const int jlg = tid & 15;
    float hprev[4];
    #pragma unroll
    for (int i = 0; i < 4; i++)
        hprev[i] = h0[(bm0 + mg + i) * HHID + j0 + jlg];

    float2 buf[2][8][4];

#define LDX(CC, T_) {                                                         \
    _Pragma("unroll")                                                         \
    for (int s = 0; s < 8; s++) {                                             \
        int ko = ((CC) * 8 + s) * 16;                                         \
        const float* p0 = bx0 + (size_t)(T_) * II + ko;                       \
        const float* p1 = bx1 + (size_t)(T_) * II + ko;                       \
        buf[(CC) & 1][s][0] = *(const float2*)p0;                             \
        buf[(CC) & 1][s][1] = *(const float2*)p1;                             \
        buf[(CC) & 1][s][2] = *(const float2*)(p0 + 8);                       \
        buf[(CC) & 1][s][3] = *(const float2*)(p1 + 8);                       \
    } }
#define LDH(CC) {                                                             \
    _Pragma("unroll")                                                         \
    for (int s = 0; s < 8; s++) {                                             \
        int ko = ((CC) * 8 + s) * 16 - II;                                    \
        const float* p0 = bh0 + ko;                                           \
        const float* p1 = bh1 + ko;                                           \
        buf[(CC) & 1][s][0] = *(const float2*)p0;                             \
        buf[(CC) & 1][s][1] = *(const float2*)p1;                             \
        buf[(CC) & 1][s][2] = *(const float2*)(p0 + 8);                       \
        buf[(CC) & 1][s][3] = *(const float2*)(p1 + 8);                       \
    } }
#define CMP(CC, ACC) {                                                        \
    _Pragma("unroll")                                                         \
    for (int s = 0; s < 8; s++) {                                             \
        uint32_t kb = (uint32_t)(((CC) * 8 + s) * 32);                        \
        unsigned ah[4], al[4];                                                \
        cvt_hilo(buf[(CC) & 1][s][0], ah[0], al[0]);                          \
        cvt_hilo(buf[(CC) & 1][s][1], ah[1], al[1]);                          \
        cvt_hilo(buf[(CC) & 1][s][2], ah[2], al[2]);                          \
        cvt_hilo(buf[(CC) & 1][s][3], ah[3], al[3]);                          \
        unsigned h0r, h1r, h2r, h3r, h4r, h5r;                                \
        unsigned l0r, l1r, l2r, l3r, l4r, l5r;                                \
        ldsm4(a4base + kb, h0r, h1r, h2r, h3r);                               \
        ldsm2(a2base + kb, h4r, h5r);                                         \
        ldsm4(a4base + WLO + kb, l0r, l1r, l2r, l3r);                         \
        ldsm2(a2base + WLO + kb, l4r, l5r);                                   \
        mma_bf16(ACC[0], ah, h0r, h1r);                                       \
        mma_bf16(ACC[1], ah, h2r, h3r);                                       \
        mma_bf16(ACC[2], ah, h4r, h5r);                                       \
        mma_bf16(ACC[0], ah, l0r, l1r);                                       \
        mma_bf16(ACC[1], ah, l2r, l3r);                                       \
        mma_bf16(ACC[2], ah, l4r, l5r);                                       \
        mma_bf16(ACC[0], al, h0r, h1r);                                       \
        mma_bf16(ACC[1], al, h2r, h3r);                                       \
        mma_bf16(ACC[2], al, h4r, h5r);                                       \
    } }

    LDX(0, 0);   // prefetch first x chunk

    for (int t = 0; t < TT; t++) {
        const float* hrd = (t == 0) ? h0 : g_h[(t + 1) & 1];
        const float* bh0 = hrd + (bm0 + wm + rl) * HHID + c2;
        const float* bh1 = bh0 + 8 * HHID;

        float accX[3][4] = {{0,0,0,0},{0,0,0,0},{0,0,0,0}};
        float accH[3][4] = {{0,0,0,0},{0,0,0,0},{0,0,0,0}};

        LDX(1, t);  CMP(0, accX);
        LDH(2);     CMP(1, accX);
        LDH(3);     CMP(2, accH);
        LDH(4);     CMP(3, accH);
        LDH(5);     CMP(4, accH);
                    CMP(5, accH);
        if (t + 1 < TT) LDX(0, t + 1);   // next step's x, pre-barrier

        // ---- frags -> SMEM scratch ----
        #pragma unroll
        for (int nf = 0; nf < 3; nf++) {
            int n0 = wn + nf * 8 + (lane & 3) * 2;
            int r0 = wm + (lane >> 2);
            scrX[n0 * 33 + r0]           = accX[nf][0];
            scrX[(n0 + 1) * 33 + r0]     = accX[nf][1];
            scrX[n0 * 33 + r0 + 8]       = accX[nf][2];
            scrX[(n0 + 1) * 33 + r0 + 8] = accX[nf][3];
            scrH[n0 * 33 + r0]           = accH[nf][0];
            scrH[(n0 + 1) * 33 + r0]     = accH[nf][1];
            scrH[n0 * 33 + r0 + 8]       = accH[nf][2];
            scrH[(n0 + 1) * 33 + r0 + 8] = accH[nf][3];
        }
        __syncthreads();

        // ---- gates: thread owns (b = bm0+mg+i, j = j0+jlg) ----
        #pragma unroll
        for (int i = 0; i < 4; i++) {
            int m = mg + i;
            float xr = scrX[jlg * 33 + m];
            float xz = scrX[(16 + jlg) * 33 + m];
            float xn = scrX[(32 + jlg) * 33 + m];
            float hr = scrH[jlg * 33 + m];
            float hz = scrH[(16 + jlg) * 33 + m];
            float hh = scrH[(32 + jlg) * 33 + m];
            float r  = 1.f / (1.f + __expf(-(xr + hr + bias[jlg])));
            float z  = 1.f / (1.f + __expf(-(xz + hz + bias[16 + jlg])));
            float n  = tanhf(xn + bias[32 + jlg] + r * (hh + bias[48 + jlg]));
            float hn = (1.f - z) * n + z * hprev[i];
            hprev[i] = hn;
            g_h[t & 1][(bm0 + m) * HHID + j0 + jlg] = hn;
            if (t == TT - 1) {
                int o = (bm0 + m) * 2048 + j0 + jlg;
                out[o]                   = r;  out[o + 262144]          = r;
                out[o + 512]             = z;  out[o + 512 + 262144]    = z;
                out[o + 1024]            = n;  out[o + 1024 + 262144]   = n;
                out[o + 1536]            = hn; out[o + 1536 + 262144]   = hn;
            }
        }

        // ---- grid barrier (128 CTAs, single wave) ----
        if (t < TT - 1) {
            __threadfence();
            __syncthreads();
            if (tid == 0) {
                int old = atomicAdd(&g_count, 1);
                if (old == GRID - 1) {
                    g_count = 0;
                    __threadfence();
                    g_flag = t + 1;
                } else {
                    while (g_flag < t + 1) { }
                    __threadfence();
                }
            }
            __syncthreads();
        }
    }

    // ---- reset barrier state for next graph replay ----
    __syncthreads();
    if (tid == 0) {
        int old = atomicAdd(&g_count, 1);
        if (old == GRID - 1) {
            g_count = 0;
            g_flag  = 0;
            __threadfence();
        }
    }
}

extern "C" void kernel_launch(void* const* d_in, const int* in_sizes, int n_in,
                              void* d_out, int out_size) {
    const float* x   = (const float*)d_in[0];
    const float* h   = (const float*)d_in[1];
    const float* Wih = (const float*)d_in[2];
    const float* bih = (const float*)d_in[3];
    const float* Whh = (const float*)d_in[4];
    const float* bhh = (const float*)d_in[5];
    float* out = (float*)d_out;

    cudaFuncSetAttribute(gru_mma, cudaFuncAttributeMaxDynamicSharedMemorySize,
                         SMEM_BYTES);
    gru_mma<<<GRID, NTHREADS, SMEM_BYTES>>>(x, h, Wih, bih, Whh, bhh, out);
}